// round 2
// baseline (speedup 1.0000x reference)
#include <cuda_runtime.h>
#include <math.h>
#include <stddef.h>

// ---------------------------------------------------------------------------
// Problem constants
// ---------------------------------------------------------------------------
#define BATCH   2
#define SEQL    2048
#define DIM     4096
#define NH      32
#define NKV     8
#define HEADD   128
#define HIDDEN  11008
#define TOK     (BATCH * SEQL)        /* 4096 tokens   */
#define QD      (NH  * HEADD)         /* 4096          */
#define KVD     (NKV * HEADD)         /* 1024          */

// ---------------------------------------------------------------------------
// Scratch (static device globals; allocation-free per harness rules) ~520 MB
// ---------------------------------------------------------------------------
__device__ float g_q [(size_t)TOK * QD];      //  64 MB (q, then attn out)
__device__ float g_k [(size_t)TOK * KVD];     //  16 MB
__device__ float g_v [(size_t)TOK * KVD];     //  16 MB
__device__ float g_h [(size_t)TOK * DIM];     //  64 MB (residual h)
__device__ float g_f1[(size_t)TOK * HIDDEN];  // 180 MB
__device__ float g_f3[(size_t)TOK * HIDDEN];  // 180 MB

// ---------------------------------------------------------------------------
// fp32 GEMM: C = alpha * A @ B (+ resid). A[M,K] lda, B[K,N] ldb, C[M,N] ldc.
// 128x128 tile, BK=8, 256 threads, 8x8 register tile. Dims divide tiles.
// ---------------------------------------------------------------------------
__global__ void __launch_bounds__(256) sgemm_nn(
    const float* __restrict__ A, const float* __restrict__ Bm,
    const float* __restrict__ resid, float* __restrict__ C,
    int M, int N, int K, int lda, int ldb, int ldc, float alpha)
{
    constexpr int BK = 8;
    __shared__ float As[BK][128];
    __shared__ float Bs[BK][128];

    const int tid = threadIdx.x;
    const int m0  = blockIdx.y * 128;
    const int n0  = blockIdx.x * 128;
    const int tx  = tid & 15;
    const int ty  = tid >> 4;
    const int lrow = tid >> 1;
    const int lcol = (tid & 1) * 4;
    const int brow = tid >> 5;
    const int bcol = (tid & 31) * 4;

    float acc[8][8];
#pragma unroll
    for (int i = 0; i < 8; i++)
#pragma unroll
        for (int j = 0; j < 8; j++) acc[i][j] = 0.f;

    for (int k0 = 0; k0 < K; k0 += BK) {
        float4 av = *(const float4*)(A + (size_t)(m0 + lrow) * lda + k0 + lcol);
        As[lcol + 0][lrow] = av.x;
        As[lcol + 1][lrow] = av.y;
        As[lcol + 2][lrow] = av.z;
        As[lcol + 3][lrow] = av.w;
        float4 bv = *(const float4*)(Bm + (size_t)(k0 + brow) * ldb + n0 + bcol);
        *(float4*)(&Bs[brow][bcol]) = bv;
        __syncthreads();

#pragma unroll
        for (int kk = 0; kk < BK; kk++) {
            float ar[8], br[8];
            *(float4*)(ar)     = *(const float4*)(&As[kk][ty * 8]);
            *(float4*)(ar + 4) = *(const float4*)(&As[kk][ty * 8 + 4]);
            *(float4*)(br)     = *(const float4*)(&Bs[kk][tx * 8]);
            *(float4*)(br + 4) = *(const float4*)(&Bs[kk][tx * 8 + 4]);
#pragma unroll
            for (int i = 0; i < 8; i++)
#pragma unroll
                for (int j = 0; j < 8; j++)
                    acc[i][j] = fmaf(ar[i], br[j], acc[i][j]);
        }
        __syncthreads();
    }

#pragma unroll
    for (int i = 0; i < 8; i++) {
        size_t rbase = (size_t)(m0 + ty * 8 + i) * ldc + n0 + tx * 8;
#pragma unroll
        for (int j = 0; j < 8; j++) {
            float v = acc[i][j] * alpha;
            if (resid) v += resid[rbase + j];
            C[rbase + j] = v;
        }
    }
}

// ---------------------------------------------------------------------------
// RoPE (interleaved pairs)
// ---------------------------------------------------------------------------
__global__ void rope_kernel(float* __restrict__ t,
                            const float* __restrict__ fcos,
                            const float* __restrict__ fsin,
                            int nheads, int npairs_total)
{
    int gid = blockIdx.x * blockDim.x + threadIdx.x;
    if (gid >= npairs_total) return;
    int i    = gid & 63;
    int rest = gid >> 6;
    int hh   = rest % nheads;
    int tok  = rest / nheads;
    int s    = tok & (SEQL - 1);
    float c  = fcos[s * 64 + i];
    float sn = fsin[s * 64 + i];
    size_t base = ((size_t)tok * nheads + hh) * HEADD + 2 * i;
    float a = t[base], b = t[base + 1];
    t[base]     = a * c - b * sn;
    t[base + 1] = a * sn + b * c;
}

// ---------------------------------------------------------------------------
// Fused causal attention (flash-style), fp32.
//   grid = (SEQL/64, BATCH*NH), block = 256 (16x16).
//   Per block: 64 query rows of one head. Online softmax, P@V in registers.
//   Output written in-place over the q buffer (same rows/cols it consumed).
// Smem: Qs[64][128] + Ks[64][132] + Vs[64][128] + Ps[64][64] = 113 KB dynamic.
// ---------------------------------------------------------------------------
#define FA_BR 64
#define FA_BC 64
#define KPAD  132

__global__ void __launch_bounds__(256) flash_kernel(
    const float* __restrict__ qin, const float* __restrict__ kin,
    const float* __restrict__ vin, float* __restrict__ oout)
{
    extern __shared__ float sm[];
    float* Qs = sm;                           // [64][128]
    float* Ks = Qs + FA_BR * HEADD;           // [64][132]
    float* Vs = Ks + FA_BC * KPAD;            // [64][128]
    float* Ps = Vs + FA_BC * HEADD;           // [64][64]

    const int z  = blockIdx.y;                // b*NH + h
    const int b  = z >> 5;
    const int h  = z & 31;
    const int kv = h >> 2;
    const int qt = blockIdx.x;
    const int q0 = qt * FA_BR;
    const int tid = threadIdx.x;
    const int tx = tid & 15;                  // cols
    const int ty = tid >> 4;                  // rows

    const float* Qg = qin + (size_t)b * SEQL * QD  + (size_t)h  * HEADD;
    const float* Kg = kin + (size_t)b * SEQL * KVD + (size_t)kv * HEADD;
    const float* Vg = vin + (size_t)b * SEQL * KVD + (size_t)kv * HEADD;
    float*       Og = oout + (size_t)b * SEQL * QD + (size_t)h  * HEADD;

    // load Q tile
    for (int idx = tid; idx < FA_BR * 32; idx += 256) {
        int r = idx >> 5, c4 = (idx & 31) << 2;
        *(float4*)&Qs[r * HEADD + c4] =
            *(const float4*)&Qg[(size_t)(q0 + r) * QD + c4];
    }

    float m[4], l[4], O[4][8];
#pragma unroll
    for (int i = 0; i < 4; i++) {
        m[i] = -1e30f; l[i] = 0.f;
#pragma unroll
        for (int d = 0; d < 8; d++) O[i][d] = 0.f;
    }

    for (int kt = 0; kt <= qt; kt++) {
        const int s0 = kt * FA_BC;
        __syncthreads();   // prev iter done with Ks/Vs/Ps
        for (int idx = tid; idx < FA_BC * 32; idx += 256) {
            int r = idx >> 5, c4 = (idx & 31) << 2;
            *(float4*)&Ks[r * KPAD  + c4] =
                *(const float4*)&Kg[(size_t)(s0 + r) * KVD + c4];
            *(float4*)&Vs[r * HEADD + c4] =
                *(const float4*)&Vg[(size_t)(s0 + r) * KVD + c4];
        }
        __syncthreads();

        // S = Q @ K^T (4x4 per thread)
        float acc[4][4];
#pragma unroll
        for (int i = 0; i < 4; i++)
#pragma unroll
            for (int j = 0; j < 4; j++) acc[i][j] = 0.f;

        for (int k4 = 0; k4 < HEADD; k4 += 4) {
            float4 qv[4], kvv[4];
#pragma unroll
            for (int i = 0; i < 4; i++)
                qv[i] = *(const float4*)&Qs[(ty * 4 + i) * HEADD + k4];
#pragma unroll
            for (int j = 0; j < 4; j++)
                kvv[j] = *(const float4*)&Ks[(tx * 4 + j) * KPAD + k4];
#pragma unroll
            for (int i = 0; i < 4; i++)
#pragma unroll
                for (int j = 0; j < 4; j++) {
                    acc[i][j] = fmaf(qv[i].x, kvv[j].x, acc[i][j]);
                    acc[i][j] = fmaf(qv[i].y, kvv[j].y, acc[i][j]);
                    acc[i][j] = fmaf(qv[i].z, kvv[j].z, acc[i][j]);
                    acc[i][j] = fmaf(qv[i].w, kvv[j].w, acc[i][j]);
                }
        }

        const bool diag = (kt == qt);
#pragma unroll
        for (int i = 0; i < 4; i++) {
            const int r = ty * 4 + i;
#pragma unroll
            for (int j = 0; j < 4; j++) {
                float s = acc[i][j] * 0.08838834764831843f;
                if (diag && (tx * 4 + j > r)) s = -1e30f;
                acc[i][j] = s;
            }
            float tm = fmaxf(fmaxf(acc[i][0], acc[i][1]),
                             fmaxf(acc[i][2], acc[i][3]));
#pragma unroll
            for (int o = 8; o; o >>= 1)
                tm = fmaxf(tm, __shfl_xor_sync(0xffffffffu, tm, o));
            float mnew = fmaxf(m[i], tm);
            float scale = __expf(m[i] - mnew);
            float4 p;
            p.x = __expf(acc[i][0] - mnew);
            p.y = __expf(acc[i][1] - mnew);
            p.z = __expf(acc[i][2] - mnew);
            p.w = __expf(acc[i][3] - mnew);
            float ts = p.x + p.y + p.z + p.w;
#pragma unroll
            for (int o = 8; o; o >>= 1)
                ts += __shfl_xor_sync(0xffffffffu, ts, o);
            l[i] = l[i] * scale + ts;
            m[i] = mnew;
#pragma unroll
            for (int d = 0; d < 8; d++) O[i][d] *= scale;
            *(float4*)&Ps[r * FA_BC + tx * 4] = p;
        }
        __syncthreads();

        // O += P @ V  (4 rows x 8 dims per thread; dims tx*8..tx*8+7)
        for (int c = 0; c < FA_BC; c++) {
            float4 va = *(const float4*)&Vs[c * HEADD + tx * 8];
            float4 vb = *(const float4*)&Vs[c * HEADD + tx * 8 + 4];
#pragma unroll
            for (int i = 0; i < 4; i++) {
                float p = Ps[(ty * 4 + i) * FA_BC + c];
                O[i][0] = fmaf(p, va.x, O[i][0]);
                O[i][1] = fmaf(p, va.y, O[i][1]);
                O[i][2] = fmaf(p, va.z, O[i][2]);
                O[i][3] = fmaf(p, va.w, O[i][3]);
                O[i][4] = fmaf(p, vb.x, O[i][4]);
                O[i][5] = fmaf(p, vb.y, O[i][5]);
                O[i][6] = fmaf(p, vb.z, O[i][6]);
                O[i][7] = fmaf(p, vb.w, O[i][7]);
            }
        }
    }

#pragma unroll
    for (int i = 0; i < 4; i++) {
        const int r = ty * 4 + i;
        const float invl = 1.0f / l[i];
        float4 oa, ob;
        oa.x = O[i][0] * invl; oa.y = O[i][1] * invl;
        oa.z = O[i][2] * invl; oa.w = O[i][3] * invl;
        ob.x = O[i][4] * invl; ob.y = O[i][5] * invl;
        ob.z = O[i][6] * invl; ob.w = O[i][7] * invl;
        *(float4*)&Og[(size_t)(q0 + r) * QD + tx * 8]     = oa;
        *(float4*)&Og[(size_t)(q0 + r) * QD + tx * 8 + 4] = ob;
    }
}

// ---------------------------------------------------------------------------
// f1 = silu(f1) * f3
// ---------------------------------------------------------------------------
__global__ void silu_mul_kernel(float* __restrict__ f1, const float* __restrict__ f3,
                                size_t n)
{
    size_t stride = (size_t)gridDim.x * blockDim.x;
    for (size_t i = (size_t)blockIdx.x * blockDim.x + threadIdx.x; i < n; i += stride) {
        float a = f1[i];
        f1[i] = a / (1.0f + __expf(-a)) * f3[i];
    }
}

// ---------------------------------------------------------------------------
// kernel_launch
// ---------------------------------------------------------------------------
extern "C" void kernel_launch(void* const* d_in, const int* in_sizes, int n_in,
                              void* d_out, int out_size)
{
    const float* x    = (const float*)d_in[0];
    /* d_in[1] = mask (unused; causal handled analytically) */
    const float* fcos = (const float*)d_in[2];
    const float* fsin = (const float*)d_in[3];
    const float* wq   = (const float*)d_in[4];
    const float* wk   = (const float*)d_in[5];
    const float* wv   = (const float*)d_in[6];
    const float* wo   = (const float*)d_in[7];
    const float* w1   = (const float*)d_in[8];
    const float* w2   = (const float*)d_in[9];
    const float* w3   = (const float*)d_in[10];
    float* out = (float*)d_out;

    float *q, *k, *v, *h, *f1, *f3;
    cudaGetSymbolAddress((void**)&q,  g_q);
    cudaGetSymbolAddress((void**)&k,  g_k);
    cudaGetSymbolAddress((void**)&v,  g_v);
    cudaGetSymbolAddress((void**)&h,  g_h);
    cudaGetSymbolAddress((void**)&f1, g_f1);
    cudaGetSymbolAddress((void**)&f3, g_f3);

    const int fa_smem = (FA_BR * HEADD + FA_BC * KPAD + FA_BC * HEADD +
                         FA_BR * FA_BC) * (int)sizeof(float);
    cudaFuncSetAttribute(flash_kernel,
                         cudaFuncAttributeMaxDynamicSharedMemorySize, fa_smem);

    const dim3 blk(256);

    // QKV projections
    sgemm_nn<<<dim3(QD  / 128, TOK / 128), blk>>>(x, wq, nullptr, q, TOK, QD,  DIM, DIM, QD,  QD,  1.f);
    sgemm_nn<<<dim3(KVD / 128, TOK / 128), blk>>>(x, wk, nullptr, k, TOK, KVD, DIM, DIM, KVD, KVD, 1.f);
    sgemm_nn<<<dim3(KVD / 128, TOK / 128), blk>>>(x, wv, nullptr, v, TOK, KVD, DIM, DIM, KVD, KVD, 1.f);

    // RoPE on q and k
    {
        int nq = TOK * NH  * 64;
        int nk = TOK * NKV * 64;
        rope_kernel<<<(nq + 255) / 256, 256>>>(q, fcos, fsin, NH,  nq);
        rope_kernel<<<(nk + 255) / 256, 256>>>(k, fcos, fsin, NKV, nk);
    }

    // fused causal attention; output overwrites q (same layout)
    flash_kernel<<<dim3(SEQL / FA_BR, BATCH * NH), blk, fa_smem>>>(q, k, v, q);

    // h = x + attn @ wo
    sgemm_nn<<<dim3(DIM / 128, TOK / 128), blk>>>(q, wo, x, h, TOK, DIM, QD, QD, DIM, DIM, 1.f);

    // FFN
    sgemm_nn<<<dim3(HIDDEN / 128, TOK / 128), blk>>>(h, w1, nullptr, f1, TOK, HIDDEN, DIM, DIM, HIDDEN, HIDDEN, 1.f);
    sgemm_nn<<<dim3(HIDDEN / 128, TOK / 128), blk>>>(h, w3, nullptr, f3, TOK, HIDDEN, DIM, DIM, HIDDEN, HIDDEN, 1.f);
    silu_mul_kernel<<<4096, 256>>>(f1, f3, (size_t)TOK * HIDDEN);

    // out = h + (silu-gated) @ w2
    sgemm_nn<<<dim3(DIM / 128, TOK / 128), blk>>>(f1, w2, h, out, TOK, DIM, HIDDEN, HIDDEN, DIM, DIM, 1.f);
}

// round 4
// speedup vs baseline: 2.3540x; 2.3540x over previous
#include <cuda_runtime.h>
#include <cuda_bf16.h>
#include <math.h>
#include <stddef.h>
#include <stdint.h>

// ---------------------------------------------------------------------------
// Problem constants
// ---------------------------------------------------------------------------
#define BATCH   2
#define SEQL    2048
#define DIM     4096
#define NH      32
#define NKV     8
#define HEADD   128
#define HIDDEN  11008
#define TOK     (BATCH * SEQL)        /* 4096 */
#define QD      (NH  * HEADD)         /* 4096 */
#define KVD     (NKV * HEADD)         /* 1024 */
#define MAXEL   ((size_t)TOK * HIDDEN)

// ---------------------------------------------------------------------------
// Scratch (static device globals; allocation-free per harness rules)
// ---------------------------------------------------------------------------
__device__ float g_q [(size_t)TOK * QD];
__device__ float g_k [(size_t)TOK * KVD];
__device__ float g_v [(size_t)TOK * KVD];
__device__ float g_h [(size_t)TOK * DIM];
__device__ float g_f1[(size_t)TOK * HIDDEN];
__device__ float g_f3[(size_t)TOK * HIDDEN];
__device__ __nv_bfloat16 g_ahi[MAXEL];
__device__ __nv_bfloat16 g_alo[MAXEL];
__device__ __nv_bfloat16 g_whi[MAXEL];
__device__ __nv_bfloat16 g_wlo[MAXEL];

// ---------------------------------------------------------------------------
// PTX helpers (sm_100-safe: cp.async / ldmatrix / mma.sync only)
// ---------------------------------------------------------------------------
__device__ __forceinline__ uint32_t smem_u32(const void* p) {
    uint32_t a;
    asm("{ .reg .u64 t; cvta.to.shared.u64 t, %1; cvt.u32.u64 %0, t; }"
        : "=r"(a) : "l"(p));
    return a;
}
#define CP_ASYNC16(dst, src) \
    asm volatile("cp.async.cg.shared.global [%0], [%1], 16;" \
                 :: "r"(dst), "l"(src) : "memory")
#define CP_COMMIT() asm volatile("cp.async.commit_group;" ::: "memory")
#define CP_WAIT0()  asm volatile("cp.async.wait_group 0;" ::: "memory")
#define CP_WAIT1()  asm volatile("cp.async.wait_group 1;" ::: "memory")

#define LDMX4(r0, r1, r2, r3, addr) \
    asm volatile("ldmatrix.sync.aligned.m8n8.x4.shared.b16 {%0,%1,%2,%3}, [%4];" \
                 : "=r"(r0), "=r"(r1), "=r"(r2), "=r"(r3) : "r"(addr))

#define MMA16816(c0, c1, c2, c3, a0, a1, a2, a3, b0, b1) \
    asm volatile("mma.sync.aligned.m16n8k16.row.col.f32.bf16.bf16.f32 " \
                 "{%0,%1,%2,%3}, {%4,%5,%6,%7}, {%8,%9}, {%0,%1,%2,%3};" \
                 : "+f"(c0), "+f"(c1), "+f"(c2), "+f"(c3) \
                 : "r"(a0), "r"(a1), "r"(a2), "r"(a3), "r"(b0), "r"(b1))

// ---------------------------------------------------------------------------
// bf16 HMMA GEMM: C[M,N] = sum of 3 passes (Ahi*Bhi + Ahi*Blo + Alo*Bhi) + resid
// A*: [M,K] bf16 row-major. B*: [N,K] bf16 row-major (W^T, K-major = mma .col).
// 128x128 CTA tile, 256 thr (8 warps, 2Mx4N), BK=64, double-buffered cp.async,
// SW128-xor swizzled smem, ldmatrix.x4 operand loads. 64 KB dynamic smem.
// ---------------------------------------------------------------------------
#define GEMM_SMEM 65536
#define STG 32768           /* bytes per stage (A 16K + B 16K) */

__global__ void __launch_bounds__(256) mma_gemm(
    const __nv_bfloat16* __restrict__ Ahi, const __nv_bfloat16* __restrict__ Alo,
    const __nv_bfloat16* __restrict__ Bhi, const __nv_bfloat16* __restrict__ Blo,
    const float* __restrict__ resid, float* __restrict__ C,
    int K, int ldc)
{
    extern __shared__ char smc[];
    const uint32_t sbase = smem_u32(smc);
    const int tid   = threadIdx.x;
    const int lane  = tid & 31;
    const int wid   = tid >> 5;
    const int warpM = wid >> 2;          // 0..1
    const int warpN = wid & 3;           // 0..3
    const int m0 = blockIdx.y * 128;
    const int n0 = blockIdx.x * 128;

    const int nk = K >> 6;               // 64-wide K chunks per pass
    const int NC = 3 * nk;

    float acc[4][4][4];
#pragma unroll
    for (int mt = 0; mt < 4; mt++)
#pragma unroll
        for (int nt = 0; nt < 4; nt++)
#pragma unroll
            for (int e = 0; e < 4; e++) acc[mt][nt][e] = 0.f;

    // per-thread load slots: 4 x 16B for A, 4 x 16B for B
    const int lr = tid >> 1;             // rows handled: lr, lr+... pattern below
    (void)lr;

    auto load_chunk = [&](int c, int stage) {
        const int p  = c / nk;
        const int k0 = (c - p * nk) << 6;
        const __nv_bfloat16* As = (p == 2) ? Alo : Ahi;
        const __nv_bfloat16* Bs = (p == 1) ? Blo : Bhi;
        const uint32_t uA = sbase + stage * STG;
        const uint32_t uB = uA + 16384;
#pragma unroll
        for (int it = 0; it < 4; it++) {
            const int idx = tid + it * 256;          // 0..1023
            const int r  = idx >> 3;                 // 0..127
            const int cc = idx & 7;                  // 16B column
            uint32_t o = (uint32_t)(r * 128 + cc * 16);
            o ^= (o >> 3) & 0x70;
            CP_ASYNC16(uA + o, As + (size_t)(m0 + r) * K + k0 + cc * 8);
            CP_ASYNC16(uB + o, Bs + (size_t)(n0 + r) * K + k0 + cc * 8);
        }
    };

    auto compute_chunk = [&](int stage) {
        const uint32_t uA = sbase + stage * STG;
        const uint32_t uB = uA + 16384;
#pragma unroll
        for (int ks = 0; ks < 4; ks++) {
            const int kb = ks * 32;                  // byte offset of k16 step
            uint32_t a[4][4];
#pragma unroll
            for (int mt = 0; mt < 4; mt++) {
                const int r = warpM * 64 + mt * 16 + (lane & 15);
                const int cbyte = kb + ((lane >> 4) << 4);
                uint32_t o = (uint32_t)(r * 128 + cbyte);
                o ^= (o >> 3) & 0x70;
                LDMX4(a[mt][0], a[mt][1], a[mt][2], a[mt][3], uA + o);
            }
            uint32_t bf[2][4];
#pragma unroll
            for (int g = 0; g < 2; g++) {
                const int r = warpN * 32 + g * 16 + (lane & 7) + ((lane >> 4) << 3);
                const int cbyte = kb + (((lane >> 3) & 1) << 4);
                uint32_t o = (uint32_t)(r * 128 + cbyte);
                o ^= (o >> 3) & 0x70;
                LDMX4(bf[g][0], bf[g][1], bf[g][2], bf[g][3], uB + o);
            }
#pragma unroll
            for (int mt = 0; mt < 4; mt++)
#pragma unroll
                for (int nt = 0; nt < 4; nt++) {
                    const uint32_t b0 = bf[nt >> 1][(nt & 1) * 2];
                    const uint32_t b1 = bf[nt >> 1][(nt & 1) * 2 + 1];
                    MMA16816(acc[mt][nt][0], acc[mt][nt][1],
                             acc[mt][nt][2], acc[mt][nt][3],
                             a[mt][0], a[mt][1], a[mt][2], a[mt][3], b0, b1);
                }
        }
    };

    load_chunk(0, 0);
    CP_COMMIT();

    for (int i = 0; i < NC; i++) {
        const int b = i & 1;
        if (i + 1 < NC) {
            load_chunk(i + 1, b ^ 1);
            CP_COMMIT();
            CP_WAIT1();            // stage i ready, i+1 in flight
        } else {
            CP_WAIT0();
        }
        __syncthreads();
        compute_chunk(b);
        __syncthreads();           // done with stage b before it is refilled
    }

    // epilogue: direct global stores (+ optional residual)
    const int g  = lane >> 2;
    const int tg = lane & 3;
#pragma unroll
    for (int mt = 0; mt < 4; mt++) {
        const int row = m0 + warpM * 64 + mt * 16 + g;
#pragma unroll
        for (int nt = 0; nt < 4; nt++) {
            const int col = n0 + warpN * 32 + nt * 8 + tg * 2;
            const size_t i0 = (size_t)row * ldc + col;
            const size_t i1 = (size_t)(row + 8) * ldc + col;
            float2 v0 = make_float2(acc[mt][nt][0], acc[mt][nt][1]);
            float2 v1 = make_float2(acc[mt][nt][2], acc[mt][nt][3]);
            if (resid) {
                float2 r0 = *(const float2*)(resid + i0);
                float2 r1 = *(const float2*)(resid + i1);
                v0.x += r0.x; v0.y += r0.y;
                v1.x += r1.x; v1.y += r1.y;
            }
            *(float2*)(C + i0) = v0;
            *(float2*)(C + i1) = v1;
        }
    }
}

// ---------------------------------------------------------------------------
// fp32 -> bf16 hi/lo split (row-major, elementwise)
// ---------------------------------------------------------------------------
__global__ void split_kernel(const float* __restrict__ src,
                             __nv_bfloat16* __restrict__ hi,
                             __nv_bfloat16* __restrict__ lo, size_t n)
{
    const size_t stride = (size_t)gridDim.x * blockDim.x;
    for (size_t i = (size_t)blockIdx.x * blockDim.x + threadIdx.x; i < n; i += stride) {
        float v = src[i];
        __nv_bfloat16 h = __float2bfloat16(v);
        hi[i] = h;
        lo[i] = __float2bfloat16(v - __bfloat162float(h));
    }
}

// W [K,N] fp32 -> W^T [N,K] bf16 hi/lo.  grid=(N/32, K/32), block=(32,8)
__global__ void split_transpose_kernel(const float* __restrict__ W,
                                       __nv_bfloat16* __restrict__ hi,
                                       __nv_bfloat16* __restrict__ lo,
                                       int K, int N)
{
    __shared__ float t[32][33];
    const int nb = blockIdx.x * 32, kb = blockIdx.y * 32;
    const int tx = threadIdx.x, ty = threadIdx.y;
#pragma unroll
    for (int j = 0; j < 4; j++)
        t[ty + j * 8][tx] = W[(size_t)(kb + ty + j * 8) * N + nb + tx];
    __syncthreads();
#pragma unroll
    for (int j = 0; j < 4; j++) {
        const int n = nb + ty + j * 8;
        const float v = t[tx][ty + j * 8];
        __nv_bfloat16 h = __float2bfloat16(v);
        hi[(size_t)n * K + kb + tx] = h;
        lo[(size_t)n * K + kb + tx] = __float2bfloat16(v - __bfloat162float(h));
    }
}

// ---------------------------------------------------------------------------
// RoPE (interleaved pairs)
// ---------------------------------------------------------------------------
__global__ void rope_kernel(float* __restrict__ t,
                            const float* __restrict__ fcos,
                            const float* __restrict__ fsin,
                            int nheads, int npairs_total)
{
    int gid = blockIdx.x * blockDim.x + threadIdx.x;
    if (gid >= npairs_total) return;
    int i    = gid & 63;
    int rest = gid >> 6;
    int hh   = rest % nheads;
    int tok  = rest / nheads;
    int s    = tok & (SEQL - 1);
    float c  = fcos[s * 64 + i];
    float sn = fsin[s * 64 + i];
    size_t base = ((size_t)tok * nheads + hh) * HEADD + 2 * i;
    float a = t[base], b = t[base + 1];
    t[base]     = a * c - b * sn;
    t[base + 1] = a * sn + b * c;
}

// ---------------------------------------------------------------------------
// Fused causal flash attention, fp32 (unchanged from passing round 2)
// ---------------------------------------------------------------------------
#define FA_BR 64
#define FA_BC 64
#define KPAD  132

__global__ void __launch_bounds__(256) flash_kernel(
    const float* __restrict__ qin, const float* __restrict__ kin,
    const float* __restrict__ vin, float* __restrict__ oout)
{
    extern __shared__ float smf[];
    float* Qs = smf;
    float* Ks = Qs + FA_BR * HEADD;
    float* Vs = Ks + FA_BC * KPAD;
    float* Ps = Vs + FA_BC * HEADD;

    const int z  = blockIdx.y;
    const int b  = z >> 5;
    const int h  = z & 31;
    const int kv = h >> 2;
    const int qt = blockIdx.x;
    const int q0 = qt * FA_BR;
    const int tid = threadIdx.x;
    const int tx = tid & 15;
    const int ty = tid >> 4;

    const float* Qg = qin + (size_t)b * SEQL * QD  + (size_t)h  * HEADD;
    const float* Kg = kin + (size_t)b * SEQL * KVD + (size_t)kv * HEADD;
    const float* Vg = vin + (size_t)b * SEQL * KVD + (size_t)kv * HEADD;
    float*       Og = oout + (size_t)b * SEQL * QD + (size_t)h  * HEADD;

    for (int idx = tid; idx < FA_BR * 32; idx += 256) {
        int r = idx >> 5, c4 = (idx & 31) << 2;
        *(float4*)&Qs[r * HEADD + c4] =
            *(const float4*)&Qg[(size_t)(q0 + r) * QD + c4];
    }

    float m[4], l[4], O[4][8];
#pragma unroll
    for (int i = 0; i < 4; i++) {
        m[i] = -1e30f; l[i] = 0.f;
#pragma unroll
        for (int d = 0; d < 8; d++) O[i][d] = 0.f;
    }

    for (int kt = 0; kt <= qt; kt++) {
        const int s0 = kt * FA_BC;
        __syncthreads();
        for (int idx = tid; idx < FA_BC * 32; idx += 256) {
            int r = idx >> 5, c4 = (idx & 31) << 2;
            *(float4*)&Ks[r * KPAD  + c4] =
                *(const float4*)&Kg[(size_t)(s0 + r) * KVD + c4];
            *(float4*)&Vs[r * HEADD + c4] =
                *(const float4*)&Vg[(size_t)(s0 + r) * KVD + c4];
        }
        __syncthreads();

        float acc[4][4];
#pragma unroll
        for (int i = 0; i < 4; i++)
#pragma unroll
            for (int j = 0; j < 4; j++) acc[i][j] = 0.f;

        for (int k4 = 0; k4 < HEADD; k4 += 4) {
            float4 qv[4], kvv[4];
#pragma unroll
            for (int i = 0; i < 4; i++)
                qv[i] = *(const float4*)&Qs[(ty * 4 + i) * HEADD + k4];
#pragma unroll
            for (int j = 0; j < 4; j++)
                kvv[j] = *(const float4*)&Ks[(tx * 4 + j) * KPAD + k4];
#pragma unroll
            for (int i = 0; i < 4; i++)
#pragma unroll
                for (int j = 0; j < 4; j++) {
                    acc[i][j] = fmaf(qv[i].x, kvv[j].x, acc[i][j]);
                    acc[i][j] = fmaf(qv[i].y, kvv[j].y, acc[i][j]);
                    acc[i][j] = fmaf(qv[i].z, kvv[j].z, acc[i][j]);
                    acc[i][j] = fmaf(qv[i].w, kvv[j].w, acc[i][j]);
                }
        }

        const bool diag = (kt == qt);
#pragma unroll
        for (int i = 0; i < 4; i++) {
            const int r = ty * 4 + i;
#pragma unroll
            for (int j = 0; j < 4; j++) {
                float s = acc[i][j] * 0.08838834764831843f;
                if (diag && (tx * 4 + j > r)) s = -1e30f;
                acc[i][j] = s;
            }
            float tm = fmaxf(fmaxf(acc[i][0], acc[i][1]),
                             fmaxf(acc[i][2], acc[i][3]));
#pragma unroll
            for (int o = 8; o; o >>= 1)
                tm = fmaxf(tm, __shfl_xor_sync(0xffffffffu, tm, o));
            float mnew = fmaxf(m[i], tm);
            float scale = __expf(m[i] - mnew);
            float4 p;
            p.x = __expf(acc[i][0] - mnew);
            p.y = __expf(acc[i][1] - mnew);
            p.z = __expf(acc[i][2] - mnew);
            p.w = __expf(acc[i][3] - mnew);
            float ts = p.x + p.y + p.z + p.w;
#pragma unroll
            for (int o = 8; o; o >>= 1)
                ts += __shfl_xor_sync(0xffffffffu, ts, o);
            l[i] = l[i] * scale + ts;
            m[i] = mnew;
#pragma unroll
            for (int d = 0; d < 8; d++) O[i][d] *= scale;
            *(float4*)&Ps[r * FA_BC + tx * 4] = p;
        }
        __syncthreads();

        for (int c = 0; c < FA_BC; c++) {
            float4 va = *(const float4*)&Vs[c * HEADD + tx * 8];
            float4 vb = *(const float4*)&Vs[c * HEADD + tx * 8 + 4];
#pragma unroll
            for (int i = 0; i < 4; i++) {
                float p = Ps[(ty * 4 + i) * FA_BC + c];
                O[i][0] = fmaf(p, va.x, O[i][0]);
                O[i][1] = fmaf(p, va.y, O[i][1]);
                O[i][2] = fmaf(p, va.z, O[i][2]);
                O[i][3] = fmaf(p, va.w, O[i][3]);
                O[i][4] = fmaf(p, vb.x, O[i][4]);
                O[i][5] = fmaf(p, vb.y, O[i][5]);
                O[i][6] = fmaf(p, vb.z, O[i][6]);
                O[i][7] = fmaf(p, vb.w, O[i][7]);
            }
        }
    }

#pragma unroll
    for (int i = 0; i < 4; i++) {
        const int r = ty * 4 + i;
        const float invl = 1.0f / l[i];
        float4 oa, ob;
        oa.x = O[i][0] * invl; oa.y = O[i][1] * invl;
        oa.z = O[i][2] * invl; oa.w = O[i][3] * invl;
        ob.x = O[i][4] * invl; ob.y = O[i][5] * invl;
        ob.z = O[i][6] * invl; ob.w = O[i][7] * invl;
        *(float4*)&Og[(size_t)(q0 + r) * QD + tx * 8]     = oa;
        *(float4*)&Og[(size_t)(q0 + r) * QD + tx * 8 + 4] = ob;
    }
}

// ---------------------------------------------------------------------------
// f1 = silu(f1) * f3
// ---------------------------------------------------------------------------
__global__ void silu_mul_kernel(float* __restrict__ f1, const float* __restrict__ f3,
                                size_t n)
{
    size_t stride = (size_t)gridDim.x * blockDim.x;
    for (size_t i = (size_t)blockIdx.x * blockDim.x + threadIdx.x; i < n; i += stride) {
        float a = f1[i];
        f1[i] = a / (1.0f + __expf(-a)) * f3[i];
    }
}

// ---------------------------------------------------------------------------
// kernel_launch
// ---------------------------------------------------------------------------
extern "C" void kernel_launch(void* const* d_in, const int* in_sizes, int n_in,
                              void* d_out, int out_size)
{
    const float* x    = (const float*)d_in[0];
    /* d_in[1] = mask (unused; causal handled analytically) */
    const float* fcos = (const float*)d_in[2];
    const float* fsin = (const float*)d_in[3];
    const float* wq   = (const float*)d_in[4];
    const float* wk   = (const float*)d_in[5];
    const float* wv   = (const float*)d_in[6];
    const float* wo   = (const float*)d_in[7];
    const float* w1   = (const float*)d_in[8];
    const float* w2   = (const float*)d_in[9];
    const float* w3   = (const float*)d_in[10];
    float* out = (float*)d_out;

    float *q, *k, *v, *h, *f1, *f3;
    __nv_bfloat16 *ahi, *alo, *whi, *wlo;
    cudaGetSymbolAddress((void**)&q,   g_q);
    cudaGetSymbolAddress((void**)&k,   g_k);
    cudaGetSymbolAddress((void**)&v,   g_v);
    cudaGetSymbolAddress((void**)&h,   g_h);
    cudaGetSymbolAddress((void**)&f1,  g_f1);
    cudaGetSymbolAddress((void**)&f3,  g_f3);
    cudaGetSymbolAddress((void**)&ahi, g_ahi);
    cudaGetSymbolAddress((void**)&alo, g_alo);
    cudaGetSymbolAddress((void**)&whi, g_whi);
    cudaGetSymbolAddress((void**)&wlo, g_wlo);

    static int attr_done = 0;
    if (!attr_done) {
        cudaFuncSetAttribute(mma_gemm,
            cudaFuncAttributeMaxDynamicSharedMemorySize, GEMM_SMEM);
        const int fa_sm = (FA_BR * HEADD + FA_BC * KPAD + FA_BC * HEADD +
                           FA_BR * FA_BC) * (int)sizeof(float);
        cudaFuncSetAttribute(flash_kernel,
            cudaFuncAttributeMaxDynamicSharedMemorySize, fa_sm);
        attr_done = 1;
    }
    const int fa_smem = (FA_BR * HEADD + FA_BC * KPAD + FA_BC * HEADD +
                         FA_BR * FA_BC) * (int)sizeof(float);

    const dim3 tb(32, 8);

    // x -> bf16 split (shared by Q/K/V projections)
    split_kernel<<<2048, 256>>>(x, ahi, alo, (size_t)TOK * DIM);

    // Q = x @ wq
    split_transpose_kernel<<<dim3(QD / 32, DIM / 32), tb>>>(wq, whi, wlo, DIM, QD);
    mma_gemm<<<dim3(QD / 128, TOK / 128), 256, GEMM_SMEM>>>(ahi, alo, whi, wlo, nullptr, q, DIM, QD);
    // K = x @ wk
    split_transpose_kernel<<<dim3(KVD / 32, DIM / 32), tb>>>(wk, whi, wlo, DIM, KVD);
    mma_gemm<<<dim3(KVD / 128, TOK / 128), 256, GEMM_SMEM>>>(ahi, alo, whi, wlo, nullptr, k, DIM, KVD);
    // V = x @ wv
    split_transpose_kernel<<<dim3(KVD / 32, DIM / 32), tb>>>(wv, whi, wlo, DIM, KVD);
    mma_gemm<<<dim3(KVD / 128, TOK / 128), 256, GEMM_SMEM>>>(ahi, alo, whi, wlo, nullptr, v, DIM, KVD);

    // RoPE
    {
        int nq = TOK * NH  * 64;
        int nk2 = TOK * NKV * 64;
        rope_kernel<<<(nq + 255) / 256, 256>>>(q, fcos, fsin, NH,  nq);
        rope_kernel<<<(nk2 + 255) / 256, 256>>>(k, fcos, fsin, NKV, nk2);
    }

    // fused causal attention; output overwrites q
    flash_kernel<<<dim3(SEQL / FA_BR, BATCH * NH), 256, fa_smem>>>(q, k, v, q);

    // h = x + attn @ wo
    split_kernel<<<2048, 256>>>(q, ahi, alo, (size_t)TOK * QD);
    split_transpose_kernel<<<dim3(DIM / 32, QD / 32), tb>>>(wo, whi, wlo, QD, DIM);
    mma_gemm<<<dim3(DIM / 128, TOK / 128), 256, GEMM_SMEM>>>(ahi, alo, whi, wlo, x, h, QD, DIM);

    // FFN
    split_kernel<<<2048, 256>>>(h, ahi, alo, (size_t)TOK * DIM);
    split_transpose_kernel<<<dim3(HIDDEN / 32, DIM / 32), tb>>>(w1, whi, wlo, DIM, HIDDEN);
    mma_gemm<<<dim3(HIDDEN / 128, TOK / 128), 256, GEMM_SMEM>>>(ahi, alo, whi, wlo, nullptr, f1, DIM, HIDDEN);
    split_transpose_kernel<<<dim3(HIDDEN / 32, DIM / 32), tb>>>(w3, whi, wlo, DIM, HIDDEN);
    mma_gemm<<<dim3(HIDDEN / 128, TOK / 128), 256, GEMM_SMEM>>>(ahi, alo, whi, wlo, nullptr, f3, DIM, HIDDEN);

    silu_mul_kernel<<<4096, 256>>>(f1, f3, (size_t)TOK * HIDDEN);

    // out = h + gated @ w2
    split_kernel<<<4096, 256>>>(f1, ahi, alo, (size_t)TOK * HIDDEN);
    split_transpose_kernel<<<dim3(DIM / 32, HIDDEN / 32), tb>>>(w2, whi, wlo, HIDDEN, DIM);
    mma_gemm<<<dim3(DIM / 128, TOK / 128), 256, GEMM_SMEM>>>(ahi, alo, whi, wlo, h, out, HIDDEN, DIM);
}